// round 6
// baseline (speedup 1.0000x reference)
#include <cuda_runtime.h>
#include <math.h>
#include <stdint.h>

#define BATCH 8
#define HEADS 8
#define SEQ   1024
#define DIM   512
#define DH    64
#define INNER 512
#define BH    (BATCH*HEADS)   // 64

// ---------------- scratch (no allocations allowed) ----------------
__device__ float g_xn[(size_t)BATCH*SEQ*DIM];      // 16 MB
__device__ float g_q [(size_t)BH*SEQ*DH];          // 16 MB
__device__ float g_kt[(size_t)BH*DH*SEQ];          // 16 MB (K pre-transposed)
__device__ float g_v [(size_t)BH*SEQ*DH];          // 16 MB
__device__ float g_o [(size_t)BATCH*SEQ*INNER];    // 16 MB

// ---------------- helpers ----------------
__device__ __forceinline__ uint32_t f2tf32(float f) {
    uint32_t u;
    asm("cvt.rna.tf32.f32 %0, %1;" : "=r"(u) : "f"(f));
    return u;
}

__device__ __forceinline__ void mma_tf32(float c[4],
                                         const uint32_t a[4],
                                         const uint32_t b[2]) {
    asm volatile(
        "mma.sync.aligned.m16n8k8.row.col.f32.tf32.tf32.f32 "
        "{%0,%1,%2,%3}, {%4,%5,%6,%7}, {%8,%9}, {%0,%1,%2,%3};"
        : "+f"(c[0]), "+f"(c[1]), "+f"(c[2]), "+f"(c[3])
        : "r"(a[0]), "r"(a[1]), "r"(a[2]), "r"(a[3]),
          "r"(b[0]), "r"(b[1]));
}

// ---------------- LayerNorm ----------------
__global__ void ln_kernel(const float* __restrict__ x,
                          const float* __restrict__ gam,
                          const float* __restrict__ bet) {
    int row = blockIdx.x;
    const float* xr = x + (size_t)row * DIM;
    float* outp = g_xn + (size_t)row * DIM;
    int t = threadIdx.x;                      // 128 threads
    float v[4];
    float s = 0.f, ss = 0.f;
#pragma unroll
    for (int i = 0; i < 4; i++) {
        v[i] = xr[t + i*128];
        s  += v[i];
        ss += v[i]*v[i];
    }
#pragma unroll
    for (int o = 16; o; o >>= 1) {
        s  += __shfl_xor_sync(0xffffffffu, s, o);
        ss += __shfl_xor_sync(0xffffffffu, ss, o);
    }
    __shared__ float sb[2][4];
    int warp = t >> 5, lane = t & 31;
    if (lane == 0) { sb[0][warp] = s; sb[1][warp] = ss; }
    __syncthreads();
    s  = sb[0][0]+sb[0][1]+sb[0][2]+sb[0][3];
    ss = sb[1][0]+sb[1][1]+sb[1][2]+sb[1][3];
    float mean = s * (1.0f/DIM);
    float var  = ss * (1.0f/DIM) - mean*mean;
    float inv  = rsqrtf(var + 1e-5f);
#pragma unroll
    for (int i = 0; i < 4; i++) {
        int c = t + i*128;
        outp[c] = (v[i]-mean)*inv*gam[c] + bet[c];
    }
}

// ---------------- TF32 tensor-core GEMM core (for QKV / out) ----------------
template<int BM,int BN,int BK,int WM,int WN>
__device__ __forceinline__ void mma_gemm_core(
    const float* __restrict__ A, const float* __restrict__ B,
    int K, int lda, int ldb, int row0, int col0,
    float acc[WM/16][WN/8][4])
{
    constexpr int MI = WM/16, NI = WN/8;
    constexpr int WCOLS = BN/WN;
    __shared__ uint32_t As[BM][BK+4];
    __shared__ uint32_t Bs[BK][BN+8];
    const int tid  = threadIdx.x;
    const int lane = tid & 31, wid = tid >> 5;
    const int g = lane >> 2, tg = lane & 3;
    const int wr = wid / WCOLS, wc = wid % WCOLS;

#pragma unroll
    for (int mi = 0; mi < MI; mi++)
#pragma unroll
        for (int ni = 0; ni < NI; ni++)
#pragma unroll
            for (int rr = 0; rr < 4; rr++) acc[mi][ni][rr] = 0.f;

    for (int k0 = 0; k0 < K; k0 += BK) {
#pragma unroll
        for (int s = 0; s < BM*BK/4; s += 256) {
            int slot = s + tid;
            int r  = slot / (BK/4);
            int kq = slot % (BK/4);
            float4 v = *(const float4*)(A + (size_t)(row0+r)*lda + k0 + kq*4);
            As[r][kq*4+0] = f2tf32(v.x);
            As[r][kq*4+1] = f2tf32(v.y);
            As[r][kq*4+2] = f2tf32(v.z);
            As[r][kq*4+3] = f2tf32(v.w);
        }
#pragma unroll
        for (int s = 0; s < BK*BN/4; s += 256) {
            int slot = s + tid;
            int kr = slot / (BN/4);
            int nc = slot % (BN/4);
            float4 v = *(const float4*)(B + (size_t)(k0+kr)*ldb + col0 + nc*4);
            uint4 u;
            u.x = f2tf32(v.x); u.y = f2tf32(v.y);
            u.z = f2tf32(v.z); u.w = f2tf32(v.w);
            *(uint4*)&Bs[kr][nc*4] = u;
        }
        __syncthreads();
#pragma unroll
        for (int ks = 0; ks < BK/8; ks++) {
            uint32_t af[MI][4], bf[NI][2];
#pragma unroll
            for (int mi = 0; mi < MI; mi++) {
                int m0 = wr*WM + mi*16;
                af[mi][0] = As[m0+g  ][ks*8+tg  ];
                af[mi][1] = As[m0+g+8][ks*8+tg  ];
                af[mi][2] = As[m0+g  ][ks*8+tg+4];
                af[mi][3] = As[m0+g+8][ks*8+tg+4];
            }
#pragma unroll
            for (int ni = 0; ni < NI; ni++) {
                int n0 = wc*WN + ni*8;
                bf[ni][0] = Bs[ks*8+tg  ][n0+g];
                bf[ni][1] = Bs[ks*8+tg+4][n0+g];
            }
#pragma unroll
            for (int mi = 0; mi < MI; mi++)
#pragma unroll
                for (int ni = 0; ni < NI; ni++)
                    mma_tf32(acc[mi][ni], af[mi], bf[ni]);
        }
        __syncthreads();
    }
}

// ---------------- QKV projection + scatter epilogue ----------------
__global__ __launch_bounds__(256) void qkv_gemm(const float* __restrict__ w,
                                                const float* __restrict__ bias) {
    constexpr int WM = 64, WN = 32, MI = WM/16, NI = WN/8;
    float acc[MI][NI][4];
    int row0 = blockIdx.y*128, col0 = blockIdx.x*128;
    mma_gemm_core<128,128,16,WM,WN>(g_xn, w, DIM, DIM, 3*INNER, row0, col0, acc);

    const int lane = threadIdx.x & 31, wid = threadIdx.x >> 5;
    const int g = lane >> 2, tg = lane & 3;
    const int wr = wid / 4, wc = wid % 4;
#pragma unroll
    for (int mi = 0; mi < MI; mi++)
#pragma unroll
        for (int ni = 0; ni < NI; ni++)
#pragma unroll
            for (int rr = 0; rr < 4; rr++) {
                int r = row0 + wr*WM + mi*16 + g + (rr>>1)*8;
                int c = col0 + wc*WN + ni*8 + tg*2 + (rr&1);
                float val = acc[mi][ni][rr] + bias[c];
                int bb = r >> 10, nn = r & 1023;
                int sec = c >> 9, rem = c & 511;
                int h = rem >> 6, d = rem & 63;
                int bh = bb*HEADS + h;
                if (sec == 0)
                    g_q[((size_t)bh*SEQ + nn)*DH + d] = val;
                else if (sec == 1)
                    g_kt[((size_t)bh*DH + d)*SEQ + nn] = val;   // transposed
                else
                    g_v[((size_t)bh*SEQ + nn)*DH + d] = val;
            }
}

// =====================================================================
// Fused attention: scores + 4-region softmax + AV, zero HBM S traffic.
// Grid: (32 query-blocks, 64 bh). CTA = 32 queries (one image row r=qb)
// x 1024 keys. 256 threads / 8 warps; warp w owns key cols [w*128,(w+1)*128).
// Each thread holds 128 score values in registers end-to-end.
// =====================================================================
#define BKC 16            // k-chunk for scores phase

// dynamic smem layout (bytes)
#define QS_OFF   0                         // uint32 Qs[32][68]        8704
#define MSH_OFF  8704                      // float  Msh[32]           128
#define ZSH_OFF  8832                      // float  Zsh[4][32]        512
#define U_OFF    9344
// scores phase:  uint32 Bs[16][1032]   @U_OFF            66048
// softmax phase: float  red[32][33]    @U_OFF            4224
//                float  redZ[4][32][33]@U_OFF+4224       16896
// AV phase:      uint32 Wc[32][132]    @U_OFF            16896
//                uint32 Vs[128][72]    @U_OFF+16896      36864
#define SMEM_TOTAL (U_OFF + 66048)         // 75392 bytes

__global__ __launch_bounds__(256, 1) void attn_fused() {
    extern __shared__ char smem[];
    uint32_t (*Qs)[68]      = (uint32_t(*)[68])(smem + QS_OFF);
    float*    Msh           = (float*)(smem + MSH_OFF);
    float    (*Zsh)[32]     = (float(*)[32])(smem + ZSH_OFF);
    uint32_t (*Bs)[1032]    = (uint32_t(*)[1032])(smem + U_OFF);
    float    (*red)[33]     = (float(*)[33])(smem + U_OFF);
    float    (*redZ)[32][33]= (float(*)[32][33])(smem + U_OFF + 4224);
    uint32_t (*Wc)[132]     = (uint32_t(*)[132])(smem + U_OFF);
    uint32_t (*Vs)[72]      = (uint32_t(*)[72])(smem + U_OFF + 16896);

    const int qb = blockIdx.x;            // query image-row r (0..31)
    const int z  = blockIdx.y;            // bh (0..63)
    const int tid = threadIdx.x, lane = tid & 31, wid = tid >> 5;
    const int g = lane >> 2, tg = lane & 3;

    const float* Qg  = g_q  + (size_t)z*SEQ*DH + (size_t)qb*32*DH;
    const float* KTg = g_kt + (size_t)z*DH*SEQ;
    const float* Vg  = g_v  + (size_t)z*SEQ*DH;

    // ---- load Q tile 32x64 as tf32 [m][k] ----
#pragma unroll
    for (int i = 0; i < 2; i++) {
        int idx = tid + i*256;            // 512 float4 total
        int m = idx >> 4, k4 = idx & 15;
        float4 v = *(const float4*)(Qg + m*DH + k4*4);
        Qs[m][k4*4+0] = f2tf32(v.x);
        Qs[m][k4*4+1] = f2tf32(v.y);
        Qs[m][k4*4+2] = f2tf32(v.z);
        Qs[m][k4*4+3] = f2tf32(v.w);
    }

    // ---- Phase 1: scores S = Q @ K^T, 32 x 1024, in registers ----
    float acc[2][16][4];
#pragma unroll
    for (int mi = 0; mi < 2; mi++)
#pragma unroll
        for (int ni = 0; ni < 16; ni++)
#pragma unroll
            for (int rr = 0; rr < 4; rr++) acc[mi][ni][rr] = 0.f;

    for (int kc = 0; kc < DH/BKC; kc++) {
        // load B chunk: KT rows [kc*16, kc*16+16), all 1024 cols
#pragma unroll
        for (int i = 0; i < 16; i++) {
            int idx = tid + i*256;        // 4096 float4
            int r = idx >> 8, c4 = idx & 255;
            float4 v = *(const float4*)(KTg + (size_t)(kc*BKC + r)*SEQ + c4*4);
            uint4 u;
            u.x = f2tf32(v.x); u.y = f2tf32(v.y);
            u.z = f2tf32(v.z); u.w = f2tf32(v.w);
            *(uint4*)&Bs[r][c4*4] = u;
        }
        __syncthreads();
#pragma unroll
        for (int ks = 0; ks < BKC/8; ks++) {
            int kk = kc*BKC + ks*8;
            uint32_t af[2][4];
#pragma unroll
            for (int mi = 0; mi < 2; mi++) {
                af[mi][0] = Qs[mi*16+g  ][kk+tg  ];
                af[mi][1] = Qs[mi*16+g+8][kk+tg  ];
                af[mi][2] = Qs[mi*16+g  ][kk+tg+4];
                af[mi][3] = Qs[mi*16+g+8][kk+tg+4];
            }
#pragma unroll
            for (int ni = 0; ni < 16; ni++) {
                uint32_t bf[2];
                int n0 = (wid << 7) + ni*8;
                bf[0] = Bs[ks*8+tg  ][n0+g];
                bf[1] = Bs[ks*8+tg+4][n0+g];
                mma_tf32(acc[0][ni], af[0], bf);
                mma_tf32(acc[1][ni], af[1], bf);
            }
        }
        __syncthreads();
    }

    // ---- Phase 2: combined 4-region softmax (r = qb, c = local row m) ----
    // scale + per-lane local max per row-slot
    float lmax[2][2] = {{-1e30f,-1e30f},{-1e30f,-1e30f}};
#pragma unroll
    for (int mi = 0; mi < 2; mi++)
#pragma unroll
        for (int ni = 0; ni < 16; ni++)
#pragma unroll
            for (int rr = 0; rr < 4; rr++) {
                acc[mi][ni][rr] *= 0.125f;
                lmax[mi][rr>>1] = fmaxf(lmax[mi][rr>>1], acc[mi][ni][rr]);
            }
    {
        int slot = (wid << 2) | tg;
#pragma unroll
        for (int mi = 0; mi < 2; mi++)
#pragma unroll
            for (int rh = 0; rh < 2; rh++)
                red[mi*16 + rh*8 + g][slot] = lmax[mi][rh];
    }
    __syncthreads();
    {   // reduce 32 slots -> Msh[row]; 8 lanes per row
        int row = tid >> 3, l8 = tid & 7;
        float v = red[row][l8*4];
#pragma unroll
        for (int j = 1; j < 4; j++) v = fmaxf(v, red[row][l8*4+j]);
        v = fmaxf(v, __shfl_xor_sync(0xffffffffu, v, 1));
        v = fmaxf(v, __shfl_xor_sync(0xffffffffu, v, 2));
        v = fmaxf(v, __shfl_xor_sync(0xffffffffu, v, 4));
        if (l8 == 0) Msh[row] = v;
    }
    __syncthreads();

    // exp + regional partial sums
#pragma unroll
    for (int mi = 0; mi < 2; mi++)
#pragma unroll
        for (int rh = 0; rh < 2; rh++) {
            int m = mi*16 + rh*8 + g;     // local row == query col index c
            float Mv = Msh[m];
            float z0 = 0.f, z1 = 0.f, z2 = 0.f, z3 = 0.f;
#pragma unroll
            for (int ni = 0; ni < 16; ni++)
#pragma unroll
                for (int rl = 0; rl < 2; rl++) {
                    int rr = rh*2 + rl;
                    int n  = (wid << 7) + ni*8 + tg*2 + rl;
                    int ki = n >> 5, kj = n & 31;
                    float e = __expf(acc[mi][ni][rr] - Mv);
                    acc[mi][ni][rr] = e;
                    bool ple = (ki <= qb), pge = (ki >= qb);
                    bool qle = (kj <= m),  qge = (kj >= m);
                    if (ple && qle) z0 += e;
                    if (ple && qge) z1 += e;
                    if (pge && qle) z2 += e;
                    if (pge && qge) z3 += e;
                }
            int slot = (wid << 2) | tg;
            redZ[0][m][slot] = z0;
            redZ[1][m][slot] = z1;
            redZ[2][m][slot] = z2;
            redZ[3][m][slot] = z3;
        }
    __syncthreads();
    {   // reduce Z: 128 tasks (reg,row), 2 lanes each -> Zsh = 0.25/Z
        int task = tid >> 1, h = tid & 1;
        int reg = task >> 5, row = task & 31;
        float v = 0.f;
#pragma unroll
        for (int j = 0; j < 16; j++) v += redZ[reg][row][h*16 + j];
        v += __shfl_xor_sync(0xffffffffu, v, 1);
        if (h == 0) Zsh[reg][row] = 0.25f / v;
    }
    __syncthreads();

    // apply combined-weight coefficients in-register
#pragma unroll
    for (int mi = 0; mi < 2; mi++)
#pragma unroll
        for (int rh = 0; rh < 2; rh++) {
            int m = mi*16 + rh*8 + g;
            float a00 = Zsh[0][m], a01 = Zsh[1][m];
            float a10 = Zsh[2][m], a11 = Zsh[3][m];
#pragma unroll
            for (int ni = 0; ni < 16; ni++)
#pragma unroll
                for (int rl = 0; rl < 2; rl++) {
                    int rr = rh*2 + rl;
                    int n  = (wid << 7) + ni*8 + tg*2 + rl;
                    int ki = n >> 5, kj = n & 31;
                    float ct = (kj <= m ? a00 : 0.f) + (kj >= m ? a01 : 0.f);
                    float cb = (kj <= m ? a10 : 0.f) + (kj >= m ? a11 : 0.f);
                    float coef = (ki <= qb ? ct : 0.f) + (ki >= qb ? cb : 0.f);
                    acc[mi][ni][rr] *= coef;
                }
        }

    // ---- Phase 3: O = W @ V (32 x 64), W chunked through smem ----
    float acc2[2][4];
#pragma unroll
    for (int mi = 0; mi < 2; mi++)
#pragma unroll
        for (int rr = 0; rr < 4; rr++) acc2[mi][rr] = 0.f;

    for (int kc = 0; kc < 8; kc++) {
        __syncthreads();                  // Wc/Vs safe to overwrite
        if (wid == kc) {                  // owner warp stores its W chunk
#pragma unroll
            for (int mi = 0; mi < 2; mi++)
#pragma unroll
                for (int ni = 0; ni < 16; ni++)
#pragma unroll
                    for (int rr = 0; rr < 4; rr++) {
                        int m = mi*16 + (rr>>1)*8 + g;
                        int kl = ni*8 + tg*2 + (rr&1);
                        Wc[m][kl] = f2tf32(acc[mi][ni][rr]);
                    }
        }
        // all warps load V chunk [128][64]
#pragma unroll
        for (int i = 0; i < 8; i++) {
            int idx = tid + i*256;        // 2048 float4
            int k = idx >> 4, d4 = idx & 15;
            float4 v = *(const float4*)(Vg + (size_t)(kc*128 + k)*DH + d4*4);
            uint4 u;
            u.x = f2tf32(v.x); u.y = f2tf32(v.y);
            u.z = f2tf32(v.z); u.w = f2tf32(v.w);
            *(uint4*)&Vs[k][d4*4] = u;
        }
        __syncthreads();
#pragma unroll
        for (int kt = 0; kt < 16; kt++) {
            uint32_t af[2][4], bf[2];
#pragma unroll
            for (int mi = 0; mi < 2; mi++) {
                af[mi][0] = Wc[mi*16+g  ][kt*8+tg  ];
                af[mi][1] = Wc[mi*16+g+8][kt*8+tg  ];
                af[mi][2] = Wc[mi*16+g  ][kt*8+tg+4];
                af[mi][3] = Wc[mi*16+g+8][kt*8+tg+4];
            }
            bf[0] = Vs[kt*8+tg  ][wid*8+g];
            bf[1] = Vs[kt*8+tg+4][wid*8+g];
            mma_tf32(acc2[0], af[0], bf);
            mma_tf32(acc2[1], af[1], bf);
        }
    }

    // epilogue: O -> g_o[b][q][h*64+d]
    {
        int bb = z >> 3, h = z & 7;
#pragma unroll
        for (int mi = 0; mi < 2; mi++)
#pragma unroll
            for (int rr = 0; rr < 4; rr++) {
                int m = mi*16 + (rr>>1)*8 + g;
                int d = wid*8 + tg*2 + (rr&1);
                g_o[((size_t)bb*SEQ + qb*32 + m)*INNER + h*DH + d] = acc2[mi][rr];
            }
    }
}

// ---------------- output projection ----------------
__global__ __launch_bounds__(256) void out_gemm(const float* __restrict__ w,
                                                const float* __restrict__ bias,
                                                float* __restrict__ outp) {
    constexpr int WM = 64, WN = 32, MI = WM/16, NI = WN/8;
    float acc[MI][NI][4];
    int row0 = blockIdx.y*128, col0 = blockIdx.x*128;
    mma_gemm_core<128,128,16,WM,WN>(g_o, w, INNER, INNER, DIM, row0, col0, acc);
    const int lane = threadIdx.x & 31, wid = threadIdx.x >> 5;
    const int g = lane >> 2, tg = lane & 3;
    const int wr = wid / 4, wc = wid % 4;
#pragma unroll
    for (int mi = 0; mi < MI; mi++)
#pragma unroll
        for (int ni = 0; ni < NI; ni++)
#pragma unroll
            for (int rr = 0; rr < 4; rr++) {
                int r = row0 + wr*WM + mi*16 + g + (rr>>1)*8;
                int c = col0 + wc*WN + ni*8 + tg*2 + (rr&1);
                outp[(size_t)r*DIM + c] = acc[mi][ni][rr] + bias[c];
            }
}

// ---------------- launch ----------------
extern "C" void kernel_launch(void* const* d_in, const int* in_sizes, int n_in,
                              void* d_out, int out_size) {
    const float* x     = (const float*)d_in[0];
    const float* ln_g  = (const float*)d_in[1];
    const float* ln_b  = (const float*)d_in[2];
    const float* w_qkv = (const float*)d_in[3];
    const float* b_qkv = (const float*)d_in[4];
    const float* w_out = (const float*)d_in[5];
    const float* b_out = (const float*)d_in[6];
    float* outp = (float*)d_out;

    static bool attr_set = false;
    if (!attr_set) {
        cudaFuncSetAttribute(attn_fused,
                             cudaFuncAttributeMaxDynamicSharedMemorySize,
                             SMEM_TOTAL);
        attr_set = true;
    }

    ln_kernel<<<BATCH*SEQ, 128>>>(x, ln_g, ln_b);
    qkv_gemm<<<dim3((3*INNER)/128, (BATCH*SEQ)/128), 256>>>(w_qkv, b_qkv);
    attn_fused<<<dim3(32, BH), 256, SMEM_TOTAL>>>();
    out_gemm<<<dim3(DIM/128, (BATCH*SEQ)/128), 256>>>(w_out, b_out, outp);
}